// round 2
// baseline (speedup 1.0000x reference)
#include <cuda_runtime.h>
#include <cstdint>

#define NU    100000
#define NI    50000
#define NN    150000            // NU + NI
#define D     64
#define NNZ_  8000000
#define HOPS  3

// Ping-pong node-state buffers (38.4 MB each) — static __device__ per harness rules.
__device__ float g_bufA[(size_t)NN * D];   // current agg (SpMM source)
__device__ float g_bufB[(size_t)NN * D];   // accumulator  (SpMM dest)

// ---------------------------------------------------------------------------
// Init: bufA = concat(user, item); bufB = 0; out[:, hop0, :] = bufA
// One float4 per thread. out layout: node*256 + hop*64 + d (float4: node*64+hop*16+f4)
// ---------------------------------------------------------------------------
__global__ void init_kernel(const float* __restrict__ user,
                            const float* __restrict__ item,
                            float* __restrict__ out) {
    int idx = blockIdx.x * blockDim.x + threadIdx.x;
    const int total = NN * D / 4;           // 2,400,000
    if (idx >= total) return;
    const int userF4 = NU * D / 4;          // 1,600,000
    float4 v = (idx < userF4) ? ((const float4*)user)[idx]
                              : ((const float4*)item)[idx - userF4];
    ((float4*)g_bufA)[idx] = v;
    ((float4*)g_bufB)[idx] = make_float4(0.f, 0.f, 0.f, 0.f);
    int node = idx >> 4;                    // D/4 = 16 float4 per node
    int f4   = idx & 15;
    ((float4*)out)[(size_t)node * 64 + f4] = v;   // hop 0
}

// ---------------------------------------------------------------------------
// Edge-dropout SpMM: bufB[row] += 2*val * bufA[col] for kept edges (erand>=0.5).
// Warp loads 32 edges, compacts via ballot, processes kept edges 2 at a time:
// lanes 0-15 handle edge i, lanes 16-31 edge j; float4 per lane + red.v4.f32.
// ---------------------------------------------------------------------------
__global__ void spmm_kernel(const int*   __restrict__ rows,
                            const int*   __restrict__ cols,
                            const float* __restrict__ vals,
                            const float* __restrict__ erand) {
    const int gtid   = blockIdx.x * blockDim.x + threadIdx.x;
    const int warp   = gtid >> 5;
    const int lane   = gtid & 31;
    const int nwarps = (gridDim.x * blockDim.x) >> 5;
    const int sub    = lane & 15;
    const bool hi    = lane >= 16;

    const float* __restrict__ src = g_bufA;
    float*       __restrict__ dst = g_bufB;

    for (int base = warp * 32; base < NNZ_; base += nwarps * 32) {
        int e = base + lane;
        bool inb  = (e < NNZ_);
        float u   = inb ? __ldg(erand + e) : 0.f;
        bool keep = inb && (u >= 0.5f);
        float v = 0.f; int r = 0, c = 0;
        if (keep) {                         // only touch metadata for kept edges
            v = __ldg(vals + e) * 2.0f;     // 1/(1-0.5)
            r = __ldg(rows + e);
            c = __ldg(cols + e);
        }
        unsigned mask = __ballot_sync(0xFFFFFFFFu, keep);
        while (mask) {
            int l0 = __ffs(mask) - 1; mask &= mask - 1;
            int l1 = 32;
            if (mask) { l1 = __ffs(mask) - 1; mask &= mask - 1; }
            int srcl = hi ? (l1 & 31) : l0;
            float vv = __shfl_sync(0xFFFFFFFFu, v, srcl);
            int   rr = __shfl_sync(0xFFFFFFFFu, r, srcl);
            int   cc = __shfl_sync(0xFFFFFFFFu, c, srcl);
            if (!hi || l1 < 32) {
                float4 x = __ldg((const float4*)(src + (size_t)cc * D) + sub);
                x.x *= vv; x.y *= vv; x.z *= vv; x.w *= vv;
                float* addr = dst + (size_t)rr * D + sub * 4;
                asm volatile("red.global.add.v4.f32 [%0], {%1, %2, %3, %4};"
                             :: "l"(addr), "f"(x.x), "f"(x.y), "f"(x.z), "f"(x.w)
                             : "memory");
            }
        }
    }
}

// ---------------------------------------------------------------------------
// Message dropout + epilogue: a = bufB * (mrand>=0.1) / 0.9
//   out[:, hop+1, :] = a ; bufA = a ; bufB = 0 (ready for next hop / replay)
// ---------------------------------------------------------------------------
__global__ void dropout_kernel(const float* __restrict__ mrand,
                               float* __restrict__ out,
                               int hop) {
    int idx = blockIdx.x * blockDim.x + threadIdx.x;
    const int total = NN * D / 4;
    if (idx >= total) return;
    float4 a = ((float4*)g_bufB)[idx];
    float4 m = ((const float4*)mrand)[idx];
    const float s = 1.0f / 0.9f;
    a.x = (m.x >= 0.1f) ? a.x * s : 0.f;
    a.y = (m.y >= 0.1f) ? a.y * s : 0.f;
    a.z = (m.z >= 0.1f) ? a.z * s : 0.f;
    a.w = (m.w >= 0.1f) ? a.w * s : 0.f;
    ((float4*)g_bufB)[idx] = make_float4(0.f, 0.f, 0.f, 0.f);
    ((float4*)g_bufA)[idx] = a;
    int node = idx >> 4;
    int f4   = idx & 15;
    ((float4*)out)[(size_t)node * 64 + (size_t)(hop + 1) * 16 + f4] = a;
}

// ---------------------------------------------------------------------------
extern "C" void kernel_launch(void* const* d_in, const int* in_sizes, int n_in,
                              void* d_out, int out_size) {
    const float* user  = (const float*)d_in[0];
    const float* item  = (const float*)d_in[1];
    const int*   rows  = (const int*)  d_in[2];
    const int*   cols  = (const int*)  d_in[3];
    const float* vals  = (const float*)d_in[4];
    const float* erand = (const float*)d_in[5];
    const float* mrand = (const float*)d_in[6];
    float*       out   = (float*)d_out;

    const int totalF4   = NN * D / 4;
    const int ewThreads = 256;
    const int ewBlocks  = (totalF4 + ewThreads - 1) / ewThreads;   // 9375

    const int spThreads = 256;
    const int spBlocks  = 148 * 24;                                // grid-stride

    init_kernel<<<ewBlocks, ewThreads>>>(user, item, out);
    for (int hop = 0; hop < HOPS; ++hop) {
        spmm_kernel<<<spBlocks, spThreads>>>(rows, cols, vals,
                                             erand + (size_t)hop * NNZ_);
        dropout_kernel<<<ewBlocks, ewThreads>>>(mrand + (size_t)hop * NN * D,
                                                out, hop);
    }
}